// round 3
// baseline (speedup 1.0000x reference)
#include <cuda_runtime.h>
#include <cstdint>
#include <cstdio>

// Problem constants (fixed shapes for this dataset)
#define MAXN 100000
#define MAXE 1250000
#define DH   64      // D == H == 64
#define CC   40
#define KK   2

// ---------------- device scratch (static; no runtime allocation) -------------
__device__ __align__(16) float g_dis[MAXN];
__device__ int   g_deg[MAXN];
__device__ int   g_is64;
__device__ __align__(16) float g_hws[(size_t)MAXN * DH];
__device__ __align__(16) float g_agg[(size_t)MAXN * DH];
__device__ __align__(16) float g_h1 [(size_t)MAXN * DH];
__device__ __align__(16) float g_h2 [(size_t)MAXN * DH];
__device__ __align__(16) float g_ego[(size_t)MAXN * DH];

// ---------------- helpers ----------------------------------------------------
__device__ __forceinline__ long long edge_at(const void* ei, long long pos) {
    if (g_is64) return ((const long long*)ei)[pos];
    return (long long)((const int*)ei)[pos];
}

// Detect whether edge_index buffer is int64 or int32 (JAX x64-off silently
// downcasts). Reading 8 int64 words is in-bounds for either dtype (2E >= 16).
__global__ void k_detect(const void* ei, int n) {
    if (blockIdx.x == 0 && threadIdx.x == 0) {
        const long long* p = (const long long*)ei;
        int ok = 1;
        #pragma unroll
        for (int k = 0; k < 8; k++) {
            long long v = p[k];
            if (v < 0 || v >= (long long)n) ok = 0;
        }
        g_is64 = ok;
    }
}

__global__ void k_deg_init(int n) {
    int i = blockIdx.x * blockDim.x + threadIdx.x;
    if (i < n) g_deg[i] = 1;   // self-loop
}

__global__ void k_count(const void* ei, int E) {
    int e = blockIdx.x * blockDim.x + threadIdx.x;
    if (e < E) {
        int c = (int)edge_at(ei, (long long)E + e);
        atomicAdd(&g_deg[c], 1);
    }
}

__global__ void k_dis(int n) {
    int i = blockIdx.x * blockDim.x + threadIdx.x;
    if (i < n) g_dis[i] = rsqrtf((float)g_deg[i]);
}

// ---------------- N x 64 x 64 GEMM with fused epilogue -----------------------
// y = act( scale[r] * (X[r] @ W) + bias );  optionally mirrored into out2
// (out2 = agg initializer: carries the self-loop term hws[i] for free).
// blockDim = (16,16): tx -> 4 output cols, ty -> row within 16-row tile.
__global__ void k_gemm64(const float* __restrict__ X, const float* __restrict__ W,
                         const float* __restrict__ scale, const float* __restrict__ bias,
                         int do_relu,
                         float* __restrict__ out, float* __restrict__ out2, int n)
{
    __shared__ float4 Ws[64 * 16];     // W as float4 tiles: Ws[k*16+tx]
    __shared__ float  Xs[16 * 68];     // padded rows (bank-conflict free)

    const int tx = threadIdx.x, ty = threadIdx.y;
    const int tid = ty * 16 + tx;

    const float4* Wv = (const float4*)W;
    #pragma unroll
    for (int i = tid; i < 1024; i += 256) Ws[i] = Wv[i];

    const int r = blockIdx.x * 16 + ty;
    if (r < n) {
        float4 v = ((const float4*)(X + (size_t)r * DH))[tx];
        *(float4*)&Xs[ty * 68 + tx * 4] = v;
    }
    __syncthreads();
    if (r >= n) return;

    float4 acc = make_float4(0.f, 0.f, 0.f, 0.f);
    #pragma unroll
    for (int k = 0; k < 64; k++) {
        float  xv = Xs[ty * 68 + k];
        float4 w  = Ws[k * 16 + tx];
        acc.x = fmaf(xv, w.x, acc.x);
        acc.y = fmaf(xv, w.y, acc.y);
        acc.z = fmaf(xv, w.z, acc.z);
        acc.w = fmaf(xv, w.w, acc.w);
    }
    if (scale) {
        float s = scale[r];
        acc.x *= s; acc.y *= s; acc.z *= s; acc.w *= s;
    }
    if (bias) {
        float4 b = ((const float4*)bias)[tx];
        acc.x += b.x; acc.y += b.y; acc.z += b.z; acc.w += b.w;
    }
    if (do_relu) {
        acc.x = fmaxf(acc.x, 0.f); acc.y = fmaxf(acc.y, 0.f);
        acc.z = fmaxf(acc.z, 0.f); acc.w = fmaxf(acc.w, 0.f);
    }
    ((float4*)(out + (size_t)r * DH))[tx] = acc;
    if (out2) ((float4*)(out2 + (size_t)r * DH))[tx] = acc;
}

// ---------------- edge scatter: agg[col] += hws[row] (vec4 reductions) -------
// 16 threads per edge, each handles one float4 of the 64-wide feature.
__global__ void k_scatter(const void* __restrict__ ei,
                          const float* __restrict__ src,
                          float* __restrict__ agg, int E)
{
    const int idx = blockIdx.x * blockDim.x + threadIdx.x;
    const int e = idx >> 4;
    const int j = idx & 15;
    const bool valid = (e < E);
    const int lane = threadIdx.x & 31;

    long long r0 = 0, c0 = 0;
    if (j == 0 && valid) {
        r0 = edge_at(ei, (long long)e);
        c0 = edge_at(ei, (long long)E + e);
    }
    // broadcast from the 16-thread group leader (lane 0 or 16)
    long long row = __shfl_sync(0xffffffffu, r0, lane & 16);
    long long col = __shfl_sync(0xffffffffu, c0, lane & 16);
    if (!valid) return;

    float4 v = __ldg(((const float4*)(src + (size_t)row * DH)) + j);
    float* dst = agg + (size_t)col * DH + j * 4;
    asm volatile("red.global.add.v4.f32 [%0], {%1, %2, %3, %4};"
                 :: "l"(dst), "f"(v.x), "f"(v.y), "f"(v.z), "f"(v.w)
                 : "memory");
}

// ---------------- finish: h = relu(dis[i] * agg[i] + b) ----------------------
__global__ void k_finish(const float* __restrict__ agg, const float* __restrict__ bias,
                         float* __restrict__ out, int n)
{
    int idx = blockIdx.x * blockDim.x + threadIdx.x;   // over n*16 float4s
    if (idx >= n * 16) return;
    int r = idx >> 4, j = idx & 15;
    float4 v = ((const float4*)agg)[idx];
    float  s = g_dis[r];
    float4 b = ((const float4*)bias)[j];
    float4 h;
    h.x = fmaxf(fmaf(s, v.x, b.x), 0.f);
    h.y = fmaxf(fmaf(s, v.y, b.y), 0.f);
    h.z = fmaxf(fmaf(s, v.z, b.z), 0.f);
    h.w = fmaxf(fmaf(s, v.w, b.w), 0.f);
    ((float4*)out)[idx] = h;
}

// ---------------- classifier: out = [ego|h1|h2] @ W_cls + b_cls --------------
// blockDim = (10, 20): tx -> 4 of the 40 output cols, ty -> row in 20-row tile.
__global__ void k_cls(const float* __restrict__ ego, const float* __restrict__ h1,
                      const float* __restrict__ h2,
                      const float* __restrict__ Wc, const float* __restrict__ bc,
                      float* __restrict__ out, int n)
{
    __shared__ float Ws[192 * 40];     // 30720 B
    __shared__ float Xs[20 * 196];     // padded rows, 15680 B

    const int tx = threadIdx.x, ty = threadIdx.y;
    const int tid = ty * 10 + tx;      // 0..199

    for (int i = tid; i < 192 * 40; i += 200) Ws[i] = Wc[i];

    const int r0 = blockIdx.x * 20;
    for (int i = tid; i < 20 * 192; i += 200) {
        int rr = i / 192, k = i - rr * 192;
        int gr = r0 + rr;
        float v = 0.f;
        if (gr < n) {
            if (k < 64)        v = ego[(size_t)gr * DH + k];
            else if (k < 128)  v = h1 [(size_t)gr * DH + (k - 64)];
            else               v = h2 [(size_t)gr * DH + (k - 128)];
        }
        Xs[rr * 196 + k] = v;
    }
    __syncthreads();

    const int r = r0 + ty;
    if (r >= n) return;

    float4 acc = make_float4(0.f, 0.f, 0.f, 0.f);
    #pragma unroll 8
    for (int k = 0; k < 192; k++) {
        float  xv = Xs[ty * 196 + k];
        float4 w  = *(const float4*)&Ws[k * 40 + tx * 4];
        acc.x = fmaf(xv, w.x, acc.x);
        acc.y = fmaf(xv, w.y, acc.y);
        acc.z = fmaf(xv, w.z, acc.z);
        acc.w = fmaf(xv, w.w, acc.w);
    }
    float4 b = *(const float4*)&bc[tx * 4];
    acc.x += b.x; acc.y += b.y; acc.z += b.z; acc.w += b.w;
    *(float4*)(out + (size_t)r * CC + tx * 4) = acc;
}

// ---------------- launch -----------------------------------------------------
extern "C" void kernel_launch(void* const* d_in, const int* in_sizes, int n_in,
                              void* d_out, int out_size)
{
    const float* x      = (const float*)d_in[0];
    const void*  ei     = d_in[1];
    const float* W_ego  = (const float*)d_in[2];
    const float* b_ego  = (const float*)d_in[3];
    const float* W_conv = (const float*)d_in[4];   // [2, 64, 64]
    const float* b_conv = (const float*)d_in[5];   // [2, 64]
    const float* W_cls  = (const float*)d_in[6];   // [192, 40]
    const float* b_cls  = (const float*)d_in[7];   // [40]

    const int N = in_sizes[0] / DH;
    const int E = in_sizes[1] / 2;

    // resolve device-global scratch addresses (host-side query; capture-safe)
    float *dis, *hws, *agg, *h1, *h2, *ego;
    cudaGetSymbolAddress((void**)&dis, g_dis);
    cudaGetSymbolAddress((void**)&hws, g_hws);
    cudaGetSymbolAddress((void**)&agg, g_agg);
    cudaGetSymbolAddress((void**)&h1,  g_h1);
    cudaGetSymbolAddress((void**)&h2,  g_h2);
    cudaGetSymbolAddress((void**)&ego, g_ego);

    const int T = 256;
    const dim3 gb(16, 16);
    const dim3 cb(10, 20);
    const int gemm_blocks = (N + 15) / 16;
    const long long sth = (long long)E * 16;
    const int scat_blocks = (int)((sth + T - 1) / T);
    const int fin_blocks = (N * 16 + T - 1) / T;

    // degree / normalization
    k_detect  <<<1, 32>>>(ei, N);
    k_deg_init<<<(N + T - 1) / T, T>>>(N);
    k_count   <<<(E + T - 1) / T, T>>>(ei, E);
    k_dis     <<<(N + T - 1) / T, T>>>(N);

    // hop 1: hws0 = dis * (x @ Wc0); agg init = hws0 (self-loop term)
    k_gemm64 <<<gemm_blocks, gb>>>(x, W_conv, dis, nullptr, 0, hws, agg, N);
    k_scatter<<<scat_blocks, T>>>(ei, hws, agg, E);
    k_finish <<<fin_blocks, T>>>(agg, b_conv, h1, N);

    // hop 2
    k_gemm64 <<<gemm_blocks, gb>>>(h1, W_conv + DH * DH, dis, nullptr, 0, hws, agg, N);
    k_scatter<<<scat_blocks, T>>>(ei, hws, agg, E);
    k_finish <<<fin_blocks, T>>>(agg, b_conv + DH, h2, N);

    // ego branch: relu(x @ W_ego + b_ego)
    k_gemm64 <<<gemm_blocks, gb>>>(x, W_ego, nullptr, b_ego, 1, ego, nullptr, N);

    // classifier
    k_cls<<<(N + 19) / 20, cb>>>(ego, h1, h2, W_cls, b_cls, (float*)d_out, N);
}

// round 4
// speedup vs baseline: 2.3224x; 2.3224x over previous
#include <cuda_runtime.h>
#include <cstdint>

// Problem constants (fixed shapes for this dataset)
#define MAXN 100000
#define MAXE 1250000
#define DH   64      // D == H == 64
#define CC   40

// ---------------- device scratch (static; no runtime allocation) -------------
__device__ __align__(16) float g_dis[MAXN];
__device__ int   g_deg[MAXN];
__device__ int   g_rowptr[MAXN + 1];
__device__ int   g_cur[MAXN];
__device__ int   g_csr[MAXE];
__device__ int   g_part[512];
__device__ int   g_is64;
__device__ __align__(16) float g_hws[(size_t)MAXN * DH];
__device__ __align__(16) float g_h1 [(size_t)MAXN * DH];
__device__ __align__(16) float g_h2 [(size_t)MAXN * DH];
__device__ __align__(16) float g_ego[(size_t)MAXN * DH];

// ---------------- helpers ----------------------------------------------------
__device__ __forceinline__ int edge_at(const void* ei, long long pos) {
    if (g_is64) return (int)((const long long*)ei)[pos];
    return ((const int*)ei)[pos];
}

// Detect int64 vs int32 edge buffer (JAX x64-off silently downcasts).
__global__ void k_detect(const void* ei, int n) {
    if (threadIdx.x == 0) {
        const long long* p = (const long long*)ei;
        int ok = 1;
        #pragma unroll
        for (int k = 0; k < 8; k++) {
            long long v = p[k];
            if (v < 0 || v >= (long long)n) ok = 0;
        }
        g_is64 = ok;
    }
}

__global__ void k_deg_zero(int n) {
    int i = blockIdx.x * blockDim.x + threadIdx.x;
    if (i < n) g_deg[i] = 0;
}

__global__ void k_count(const void* ei, int E) {
    int e = blockIdx.x * blockDim.x + threadIdx.x;
    if (e < E) atomicAdd(&g_deg[edge_at(ei, (long long)E + e)], 1);
}

// ---- 3-kernel exclusive scan of g_deg -> g_rowptr / g_cur; also g_dis -------
__global__ void k_scan1(int n) {          // per-block sums
    __shared__ int s[256];
    int i = blockIdx.x * 256 + threadIdx.x;
    s[threadIdx.x] = (i < n) ? g_deg[i] : 0;
    __syncthreads();
    #pragma unroll
    for (int off = 128; off > 0; off >>= 1) {
        if (threadIdx.x < off) s[threadIdx.x] += s[threadIdx.x + off];
        __syncthreads();
    }
    if (threadIdx.x == 0) g_part[blockIdx.x] = s[0];
}

__global__ void k_scan2(int nb) {         // single-block scan of partials
    __shared__ int s[512];
    int t = threadIdx.x;
    int v = (t < nb) ? g_part[t] : 0;
    s[t] = v;
    __syncthreads();
    #pragma unroll
    for (int off = 1; off < 512; off <<= 1) {
        int add = (t >= off) ? s[t - off] : 0;
        __syncthreads();
        s[t] += add;
        __syncthreads();
    }
    if (t < nb) g_part[t] = s[t] - v;     // exclusive
}

__global__ void k_scan3(int n) {          // element exclusive scan + dis
    __shared__ int s[256];
    int t = threadIdx.x;
    int i = blockIdx.x * 256 + t;
    int v = (i < n) ? g_deg[i] : 0;
    s[t] = v;
    __syncthreads();
    #pragma unroll
    for (int off = 1; off < 256; off <<= 1) {
        int add = (t >= off) ? s[t - off] : 0;
        __syncthreads();
        s[t] += add;
        __syncthreads();
    }
    if (i < n) {
        int base = g_part[blockIdx.x];
        int excl = base + s[t] - v;
        g_rowptr[i] = excl;
        g_cur[i]    = excl;
        g_dis[i]    = rsqrtf((float)(v + 1));     // +1 = self-loop
        if (i == n - 1) g_rowptr[n] = excl + v;   // == E
    }
}

__global__ void k_fill(const void* ei, int E) {
    int e = blockIdx.x * blockDim.x + threadIdx.x;
    if (e < E) {
        int r = edge_at(ei, (long long)e);
        int c = edge_at(ei, (long long)E + e);
        int pos = atomicAdd(&g_cur[c], 1);
        g_csr[pos] = r;
    }
}

// ---------------- N x 64 x 64 GEMM, 4x4 register tile -------------------------
// out[r] = act( s[r] * (X[r] @ W) + bias )   (s = g_dis if use_dis)
// block (16,16), tile 64 rows x 64 cols.
__global__ void k_gemm64(const float* __restrict__ X, const float* __restrict__ W,
                         int use_dis, const float* __restrict__ bias, int do_relu,
                         float* __restrict__ out, int n)
{
    __shared__ float  Xs[64 * 68];
    __shared__ float4 Ws[64 * 16];

    const int tx = threadIdx.x, ty = threadIdx.y;
    const int tid = ty * 16 + tx;

    const float4* Wv = (const float4*)W;
    #pragma unroll
    for (int i = 0; i < 4; i++) Ws[tid + i * 256] = Wv[tid + i * 256];

    const int r0 = blockIdx.x * 64;
    #pragma unroll
    for (int i = 0; i < 4; i++) {
        int idx = tid + i * 256;              // 0..1023
        int rr = idx >> 4, cc = idx & 15;
        int gr = r0 + rr;
        float4 v = make_float4(0.f, 0.f, 0.f, 0.f);
        if (gr < n) v = ((const float4*)(X + (size_t)gr * DH))[cc];
        *(float4*)&Xs[rr * 68 + cc * 4] = v;
    }
    __syncthreads();

    float4 acc[4];
    #pragma unroll
    for (int i = 0; i < 4; i++) acc[i] = make_float4(0.f, 0.f, 0.f, 0.f);

    #pragma unroll
    for (int k = 0; k < 64; k++) {
        float4 w = Ws[k * 16 + tx];
        #pragma unroll
        for (int i = 0; i < 4; i++) {
            float xv = Xs[(ty * 4 + i) * 68 + k];
            acc[i].x = fmaf(xv, w.x, acc[i].x);
            acc[i].y = fmaf(xv, w.y, acc[i].y);
            acc[i].z = fmaf(xv, w.z, acc[i].z);
            acc[i].w = fmaf(xv, w.w, acc[i].w);
        }
    }

    float4 b = make_float4(0.f, 0.f, 0.f, 0.f);
    if (bias) b = ((const float4*)bias)[tx];
    #pragma unroll
    for (int i = 0; i < 4; i++) {
        int gr = r0 + ty * 4 + i;
        if (gr >= n) continue;
        float4 a = acc[i];
        if (use_dis) {
            float s = g_dis[gr];
            a.x *= s; a.y *= s; a.z *= s; a.w *= s;
        }
        a.x += b.x; a.y += b.y; a.z += b.z; a.w += b.w;
        if (do_relu) {
            a.x = fmaxf(a.x, 0.f); a.y = fmaxf(a.y, 0.f);
            a.z = fmaxf(a.z, 0.f); a.w = fmaxf(a.w, 0.f);
        }
        ((float4*)(out + (size_t)gr * DH))[tx] = a;
    }
}

// -------- CSR aggregate + finish: h = relu(dis[i]*(hws[i] + sum_nbr hws) + b) -
// warp per node; each lane owns a float2 (64 floats / 32 lanes).
__global__ void k_agg(const float* __restrict__ hws, const float* __restrict__ bias,
                      float* __restrict__ out, int n)
{
    int w = (blockIdx.x * blockDim.x + threadIdx.x) >> 5;
    int lane = threadIdx.x & 31;
    if (w >= n) return;

    const float2* H = (const float2*)hws;
    float2 acc = H[(size_t)w * 32 + lane];          // self-loop term

    int p   = g_rowptr[w];
    int end = g_rowptr[w + 1];
    for (; p + 1 < end; p += 2) {
        int s0 = g_csr[p];
        int s1 = g_csr[p + 1];
        float2 a = H[(size_t)s0 * 32 + lane];
        float2 c = H[(size_t)s1 * 32 + lane];
        acc.x += a.x + c.x;
        acc.y += a.y + c.y;
    }
    if (p < end) {
        int s0 = g_csr[p];
        float2 a = H[(size_t)s0 * 32 + lane];
        acc.x += a.x; acc.y += a.y;
    }

    float  sc = g_dis[w];
    float2 b  = ((const float2*)bias)[lane];
    float2 o;
    o.x = fmaxf(fmaf(sc, acc.x, b.x), 0.f);
    o.y = fmaxf(fmaf(sc, acc.y, b.y), 0.f);
    ((float2*)out)[(size_t)w * 32 + lane] = o;
}

// ---------------- classifier: out = [ego|h1|h2] @ W_cls + b_cls --------------
// block (10,16) = 160 threads, tile 64 rows x 40 cols, 4x4 register tile,
// K processed in 3 chunks of 64 (one per source array).
__global__ void k_cls(const float* __restrict__ ego, const float* __restrict__ h1,
                      const float* __restrict__ h2,
                      const float* __restrict__ Wc, const float* __restrict__ bc,
                      float* __restrict__ out, int n)
{
    __shared__ float4 Ws[192 * 10];    // 30720 B
    __shared__ float  Xs[64 * 68];     // 17408 B

    const int tx = threadIdx.x, ty = threadIdx.y;
    const int tid = ty * 10 + tx;      // 0..159

    const float4* Wv = (const float4*)Wc;
    #pragma unroll
    for (int i = 0; i < 12; i++) Ws[tid + i * 160] = Wv[tid + i * 160];

    const int r0 = blockIdx.x * 64;
    float4 acc[4];
    #pragma unroll
    for (int i = 0; i < 4; i++) acc[i] = make_float4(0.f, 0.f, 0.f, 0.f);

    const float* srcs[3] = {ego, h1, h2};
    for (int c = 0; c < 3; c++) {
        const float* S = srcs[c];
        __syncthreads();               // first iter also fences Ws/Xs loads
        for (int i = tid; i < 1024; i += 160) {
            int rr = i >> 4, cc = i & 15;
            int gr = r0 + rr;
            float4 v = make_float4(0.f, 0.f, 0.f, 0.f);
            if (gr < n) v = ((const float4*)(S + (size_t)gr * DH))[cc];
            *(float4*)&Xs[rr * 68 + cc * 4] = v;
        }
        __syncthreads();
        #pragma unroll
        for (int k = 0; k < 64; k++) {
            float4 w = Ws[(c * 64 + k) * 10 + tx];
            #pragma unroll
            for (int i = 0; i < 4; i++) {
                float xv = Xs[(ty * 4 + i) * 68 + k];
                acc[i].x = fmaf(xv, w.x, acc[i].x);
                acc[i].y = fmaf(xv, w.y, acc[i].y);
                acc[i].z = fmaf(xv, w.z, acc[i].z);
                acc[i].w = fmaf(xv, w.w, acc[i].w);
            }
        }
    }

    float4 b = ((const float4*)bc)[tx];
    #pragma unroll
    for (int i = 0; i < 4; i++) {
        int gr = r0 + ty * 4 + i;
        if (gr >= n) continue;
        float4 a = acc[i];
        a.x += b.x; a.y += b.y; a.z += b.z; a.w += b.w;
        *(float4*)(out + (size_t)gr * CC + tx * 4) = a;
    }
}

// ---------------- launch -----------------------------------------------------
extern "C" void kernel_launch(void* const* d_in, const int* in_sizes, int n_in,
                              void* d_out, int out_size)
{
    const float* x      = (const float*)d_in[0];
    const void*  ei     = d_in[1];
    const float* W_ego  = (const float*)d_in[2];
    const float* b_ego  = (const float*)d_in[3];
    const float* W_conv = (const float*)d_in[4];   // [2, 64, 64]
    const float* b_conv = (const float*)d_in[5];   // [2, 64]
    const float* W_cls  = (const float*)d_in[6];   // [192, 40]
    const float* b_cls  = (const float*)d_in[7];   // [40]

    const int N = in_sizes[0] / DH;
    const int E = in_sizes[1] / 2;

    float *hws, *h1, *h2, *ego;
    cudaGetSymbolAddress((void**)&hws, g_hws);
    cudaGetSymbolAddress((void**)&h1,  g_h1);
    cudaGetSymbolAddress((void**)&h2,  g_h2);
    cudaGetSymbolAddress((void**)&ego, g_ego);

    const int T = 256;
    const int NB = (N + T - 1) / T;            // node blocks (<=391)
    const int EB = (E + T - 1) / T;            // edge blocks
    const dim3 gb(16, 16);
    const dim3 cb(10, 16);
    const int tile_blocks = (N + 63) / 64;
    const int agg_blocks = (int)(((long long)N * 32 + T - 1) / T);

    // CSR build + normalization
    k_detect  <<<1, 32>>>(ei, N);
    k_deg_zero<<<NB, T>>>(N);
    k_count   <<<EB, T>>>(ei, E);
    k_scan1   <<<NB, T>>>(N);
    k_scan2   <<<1, 512>>>(NB);
    k_scan3   <<<NB, T>>>(N);
    k_fill    <<<EB, T>>>(ei, E);

    // hop 1: hws = dis * (x @ Wc0); h1 = relu(dis*(self+nbrs) + b0)
    k_gemm64<<<tile_blocks, gb>>>(x, W_conv, 1, nullptr, 0, hws, N);
    k_agg   <<<agg_blocks, T>>>(hws, b_conv, h1, N);

    // hop 2
    k_gemm64<<<tile_blocks, gb>>>(h1, W_conv + DH * DH, 1, nullptr, 0, hws, N);
    k_agg   <<<agg_blocks, T>>>(hws, b_conv + DH, h2, N);

    // ego branch: relu(x @ W_ego + b_ego)
    k_gemm64<<<tile_blocks, gb>>>(x, W_ego, 0, b_ego, 1, ego, N);

    // classifier
    k_cls<<<tile_blocks, cb>>>(ego, h1, h2, W_cls, b_cls, (float*)d_out, N);
}

// round 5
// speedup vs baseline: 2.3241x; 1.0007x over previous
#include <cuda_runtime.h>
#include <cstdint>

// Problem constants (fixed shapes for this dataset)
#define MAXN 100000
#define MAXE 1250000
#define DH   64      // D == H == 64
#define CC   40

// ---------------- device scratch (static; no runtime allocation) -------------
__device__ __align__(16) float g_dis[MAXN];
__device__ int   g_deg[MAXN];
__device__ int   g_rowptr[MAXN + 1];
__device__ int   g_cur[MAXN];
__device__ int   g_csr[MAXE];
__device__ int   g_part[512];
__device__ int   g_is64;
__device__ __align__(16) float g_hws[(size_t)MAXN * DH];
__device__ __align__(16) float g_h1 [(size_t)MAXN * DH];
__device__ __align__(16) float g_h2 [(size_t)MAXN * DH];
__device__ __align__(16) float g_ego[(size_t)MAXN * DH];

// ---------------- helpers ----------------------------------------------------
__device__ __forceinline__ int edge_at(const void* ei, long long pos) {
    if (g_is64) return (int)((const long long*)ei)[pos];
    return ((const int*)ei)[pos];
}

// deg zero + int64/int32 detection (JAX x64-off silently downcasts) in one pass
__global__ void k_deg_zero(const void* ei, int n) {
    int i = blockIdx.x * blockDim.x + threadIdx.x;
    if (i < n) g_deg[i] = 0;
    if (i == 0) {
        const long long* p = (const long long*)ei;
        int ok = 1;
        #pragma unroll
        for (int k = 0; k < 8; k++) {
            long long v = p[k];
            if (v < 0 || v >= (long long)n) ok = 0;
        }
        g_is64 = ok;
    }
}

__global__ void k_count(const void* ei, int E) {
    int e = blockIdx.x * blockDim.x + threadIdx.x;
    if (e < E) atomicAdd(&g_deg[edge_at(ei, (long long)E + e)], 1);
}

// ---- 3-kernel exclusive scan of g_deg -> g_rowptr / g_cur; also g_dis -------
__global__ void k_scan1(int n) {          // per-block sums
    __shared__ int s[256];
    int i = blockIdx.x * 256 + threadIdx.x;
    s[threadIdx.x] = (i < n) ? g_deg[i] : 0;
    __syncthreads();
    #pragma unroll
    for (int off = 128; off > 0; off >>= 1) {
        if (threadIdx.x < off) s[threadIdx.x] += s[threadIdx.x + off];
        __syncthreads();
    }
    if (threadIdx.x == 0) g_part[blockIdx.x] = s[0];
}

__global__ void k_scan2(int nb) {         // single-block scan of partials
    __shared__ int s[512];
    int t = threadIdx.x;
    int v = (t < nb) ? g_part[t] : 0;
    s[t] = v;
    __syncthreads();
    #pragma unroll
    for (int off = 1; off < 512; off <<= 1) {
        int add = (t >= off) ? s[t - off] : 0;
        __syncthreads();
        s[t] += add;
        __syncthreads();
    }
    if (t < nb) g_part[t] = s[t] - v;     // exclusive
}

__global__ void k_scan3(int n) {          // element exclusive scan + dis
    __shared__ int s[256];
    int t = threadIdx.x;
    int i = blockIdx.x * 256 + t;
    int v = (i < n) ? g_deg[i] : 0;
    s[t] = v;
    __syncthreads();
    #pragma unroll
    for (int off = 1; off < 256; off <<= 1) {
        int add = (t >= off) ? s[t - off] : 0;
        __syncthreads();
        s[t] += add;
        __syncthreads();
    }
    if (i < n) {
        int base = g_part[blockIdx.x];
        int excl = base + s[t] - v;
        g_rowptr[i] = excl;
        g_cur[i]    = excl;
        g_dis[i]    = rsqrtf((float)(v + 1));     // +1 = self-loop
        if (i == n - 1) g_rowptr[n] = excl + v;   // == E
    }
}

__global__ void k_fill(const void* ei, int E) {
    int e = blockIdx.x * blockDim.x + threadIdx.x;
    if (e < E) {
        int r = edge_at(ei, (long long)e);
        int c = edge_at(ei, (long long)E + e);
        int pos = atomicAdd(&g_cur[c], 1);
        g_csr[pos] = r;
    }
}

// ------- dual GEMM: hws = dis*(x@W1);  ego = relu(x@W2 + b2) ------------------
// block (16,16), 64-row tile, k-step-4 float4 inner loop. smem = 48KB exactly.
__global__ void k_gemm_dual(const float* __restrict__ X,
                            const float* __restrict__ W1, const float* __restrict__ W2,
                            const float* __restrict__ b2,
                            float* __restrict__ out1, float* __restrict__ out2, int n)
{
    __shared__ float  Xs[64 * 64];     // 16KB (rows differ by 256B; 2-way max)
    __shared__ float4 Ws1[64 * 16];    // 16KB
    __shared__ float4 Ws2[64 * 16];    // 16KB

    const int tx = threadIdx.x, ty = threadIdx.y;
    const int tid = ty * 16 + tx;

    const float4* W1v = (const float4*)W1;
    const float4* W2v = (const float4*)W2;
    #pragma unroll
    for (int i = 0; i < 4; i++) {
        Ws1[tid + i * 256] = W1v[tid + i * 256];
        Ws2[tid + i * 256] = W2v[tid + i * 256];
    }

    const int r0 = blockIdx.x * 64;
    #pragma unroll
    for (int i = 0; i < 4; i++) {
        int idx = tid + i * 256;              // 0..1023
        int rr = idx >> 4, cc = idx & 15;
        int gr = r0 + rr;
        float4 v = make_float4(0.f, 0.f, 0.f, 0.f);
        if (gr < n) v = ((const float4*)(X + (size_t)gr * DH))[cc];
        *(float4*)&Xs[rr * 64 + cc * 4] = v;
    }
    __syncthreads();

    float4 acc1[4], acc2[4];
    #pragma unroll
    for (int i = 0; i < 4; i++) {
        acc1[i] = make_float4(0.f, 0.f, 0.f, 0.f);
        acc2[i] = make_float4(0.f, 0.f, 0.f, 0.f);
    }

    #pragma unroll
    for (int k4 = 0; k4 < 16; k4++) {
        float4 xv[4];
        #pragma unroll
        for (int i = 0; i < 4; i++)
            xv[i] = *(const float4*)&Xs[(ty * 4 + i) * 64 + k4 * 4];
        #pragma unroll
        for (int j = 0; j < 4; j++) {
            float4 w1 = Ws1[(k4 * 4 + j) * 16 + tx];
            float4 w2 = Ws2[(k4 * 4 + j) * 16 + tx];
            #pragma unroll
            for (int i = 0; i < 4; i++) {
                float xs = (j == 0) ? xv[i].x : (j == 1) ? xv[i].y : (j == 2) ? xv[i].z : xv[i].w;
                acc1[i].x = fmaf(xs, w1.x, acc1[i].x);
                acc1[i].y = fmaf(xs, w1.y, acc1[i].y);
                acc1[i].z = fmaf(xs, w1.z, acc1[i].z);
                acc1[i].w = fmaf(xs, w1.w, acc1[i].w);
                acc2[i].x = fmaf(xs, w2.x, acc2[i].x);
                acc2[i].y = fmaf(xs, w2.y, acc2[i].y);
                acc2[i].z = fmaf(xs, w2.z, acc2[i].z);
                acc2[i].w = fmaf(xs, w2.w, acc2[i].w);
            }
        }
    }

    float4 b = ((const float4*)b2)[tx];
    #pragma unroll
    for (int i = 0; i < 4; i++) {
        int gr = r0 + ty * 4 + i;
        if (gr >= n) continue;
        float s = g_dis[gr];
        float4 a = acc1[i];
        a.x *= s; a.y *= s; a.z *= s; a.w *= s;
        ((float4*)(out1 + (size_t)gr * DH))[tx] = a;
        float4 e = acc2[i];
        e.x = fmaxf(e.x + b.x, 0.f); e.y = fmaxf(e.y + b.y, 0.f);
        e.z = fmaxf(e.z + b.z, 0.f); e.w = fmaxf(e.w + b.w, 0.f);
        ((float4*)(out2 + (size_t)gr * DH))[tx] = e;
    }
}

// ---------------- single 64x64 GEMM: out = dis * (X @ W) ---------------------
__global__ void k_gemm64(const float* __restrict__ X, const float* __restrict__ W,
                         float* __restrict__ out, int n)
{
    __shared__ float  Xs[64 * 64];
    __shared__ float4 Ws[64 * 16];

    const int tx = threadIdx.x, ty = threadIdx.y;
    const int tid = ty * 16 + tx;

    const float4* Wv = (const float4*)W;
    #pragma unroll
    for (int i = 0; i < 4; i++) Ws[tid + i * 256] = Wv[tid + i * 256];

    const int r0 = blockIdx.x * 64;
    #pragma unroll
    for (int i = 0; i < 4; i++) {
        int idx = tid + i * 256;
        int rr = idx >> 4, cc = idx & 15;
        int gr = r0 + rr;
        float4 v = make_float4(0.f, 0.f, 0.f, 0.f);
        if (gr < n) v = ((const float4*)(X + (size_t)gr * DH))[cc];
        *(float4*)&Xs[rr * 64 + cc * 4] = v;
    }
    __syncthreads();

    float4 acc[4];
    #pragma unroll
    for (int i = 0; i < 4; i++) acc[i] = make_float4(0.f, 0.f, 0.f, 0.f);

    #pragma unroll
    for (int k4 = 0; k4 < 16; k4++) {
        float4 xv[4];
        #pragma unroll
        for (int i = 0; i < 4; i++)
            xv[i] = *(const float4*)&Xs[(ty * 4 + i) * 64 + k4 * 4];
        #pragma unroll
        for (int j = 0; j < 4; j++) {
            float4 w = Ws[(k4 * 4 + j) * 16 + tx];
            #pragma unroll
            for (int i = 0; i < 4; i++) {
                float xs = (j == 0) ? xv[i].x : (j == 1) ? xv[i].y : (j == 2) ? xv[i].z : xv[i].w;
                acc[i].x = fmaf(xs, w.x, acc[i].x);
                acc[i].y = fmaf(xs, w.y, acc[i].y);
                acc[i].z = fmaf(xs, w.z, acc[i].z);
                acc[i].w = fmaf(xs, w.w, acc[i].w);
            }
        }
    }

    #pragma unroll
    for (int i = 0; i < 4; i++) {
        int gr = r0 + ty * 4 + i;
        if (gr >= n) continue;
        float s = g_dis[gr];
        float4 a = acc[i];
        a.x *= s; a.y *= s; a.z *= s; a.w *= s;
        ((float4*)(out + (size_t)gr * DH))[tx] = a;
    }
}

// -------- CSR aggregate + finish: h = relu(dis[i]*(hws[i] + sum_nbr hws) + b) -
// warp per node; each lane owns a float2; unroll-4 for MLP.
__global__ void k_agg(const float* __restrict__ hws, const float* __restrict__ bias,
                      float* __restrict__ out, int n)
{
    int w = (blockIdx.x * blockDim.x + threadIdx.x) >> 5;
    int lane = threadIdx.x & 31;
    if (w >= n) return;

    const float2* H = (const float2*)hws;
    float2 acc = H[(size_t)w * 32 + lane];          // self-loop term

    int p   = g_rowptr[w];
    int end = g_rowptr[w + 1];
    for (; p + 3 < end; p += 4) {
        int s0 = __ldg(&g_csr[p]);
        int s1 = __ldg(&g_csr[p + 1]);
        int s2 = __ldg(&g_csr[p + 2]);
        int s3 = __ldg(&g_csr[p + 3]);
        float2 a = H[(size_t)s0 * 32 + lane];
        float2 b = H[(size_t)s1 * 32 + lane];
        float2 c = H[(size_t)s2 * 32 + lane];
        float2 d = H[(size_t)s3 * 32 + lane];
        acc.x += (a.x + b.x) + (c.x + d.x);
        acc.y += (a.y + b.y) + (c.y + d.y);
    }
    for (; p < end; p++) {
        int s0 = __ldg(&g_csr[p]);
        float2 a = H[(size_t)s0 * 32 + lane];
        acc.x += a.x; acc.y += a.y;
    }

    float  sc = g_dis[w];
    float2 b  = ((const float2*)bias)[lane];
    float2 o;
    o.x = fmaxf(fmaf(sc, acc.x, b.x), 0.f);
    o.y = fmaxf(fmaf(sc, acc.y, b.y), 0.f);
    ((float2*)out)[(size_t)w * 32 + lane] = o;
}

// ---------------- classifier: out = [ego|h1|h2] @ W_cls + b_cls --------------
// block (10,16) = 160 threads, tile 64 rows x 40 cols, k-step-4 inner loop.
__global__ void k_cls(const float* __restrict__ ego, const float* __restrict__ h1,
                      const float* __restrict__ h2,
                      const float* __restrict__ Wc, const float* __restrict__ bc,
                      float* __restrict__ out, int n)
{
    __shared__ float4 Ws[192 * 10];    // 30720 B
    __shared__ float  Xs[64 * 68];     // 17408 B (stride 68: 16B-aligned rows)

    const int tx = threadIdx.x, ty = threadIdx.y;
    const int tid = ty * 10 + tx;      // 0..159

    const float4* Wv = (const float4*)Wc;
    #pragma unroll
    for (int i = 0; i < 12; i++) Ws[tid + i * 160] = Wv[tid + i * 160];

    const int r0 = blockIdx.x * 64;
    float4 acc[4];
    #pragma unroll
    for (int i = 0; i < 4; i++) acc[i] = make_float4(0.f, 0.f, 0.f, 0.f);

    const float* srcs[3] = {ego, h1, h2};
    for (int c = 0; c < 3; c++) {
        const float* S = srcs[c];
        __syncthreads();               // first iter also fences Ws/Xs loads
        for (int i = tid; i < 1024; i += 160) {
            int rr = i >> 4, cc = i & 15;
            int gr = r0 + rr;
            float4 v = make_float4(0.f, 0.f, 0.f, 0.f);
            if (gr < n) v = ((const float4*)(S + (size_t)gr * DH))[cc];
            *(float4*)&Xs[rr * 68 + cc * 4] = v;
        }
        __syncthreads();
        #pragma unroll
        for (int k4 = 0; k4 < 16; k4++) {
            float4 xv[4];
            #pragma unroll
            for (int i = 0; i < 4; i++)
                xv[i] = *(const float4*)&Xs[(ty * 4 + i) * 68 + k4 * 4];
            #pragma unroll
            for (int j = 0; j < 4; j++) {
                float4 w = Ws[(c * 64 + k4 * 4 + j) * 10 + tx];
                #pragma unroll
                for (int i = 0; i < 4; i++) {
                    float xs = (j == 0) ? xv[i].x : (j == 1) ? xv[i].y : (j == 2) ? xv[i].z : xv[i].w;
                    acc[i].x = fmaf(xs, w.x, acc[i].x);
                    acc[i].y = fmaf(xs, w.y, acc[i].y);
                    acc[i].z = fmaf(xs, w.z, acc[i].z);
                    acc[i].w = fmaf(xs, w.w, acc[i].w);
                }
            }
        }
    }

    float4 b = ((const float4*)bc)[tx];
    #pragma unroll
    for (int i = 0; i < 4; i++) {
        int gr = r0 + ty * 4 + i;
        if (gr >= n) continue;
        float4 a = acc[i];
        a.x += b.x; a.y += b.y; a.z += b.z; a.w += b.w;
        *(float4*)(out + (size_t)gr * CC + tx * 4) = a;
    }
}

// ---------------- launch -----------------------------------------------------
extern "C" void kernel_launch(void* const* d_in, const int* in_sizes, int n_in,
                              void* d_out, int out_size)
{
    const float* x      = (const float*)d_in[0];
    const void*  ei     = d_in[1];
    const float* W_ego  = (const float*)d_in[2];
    const float* b_ego  = (const float*)d_in[3];
    const float* W_conv = (const float*)d_in[4];   // [2, 64, 64]
    const float* b_conv = (const float*)d_in[5];   // [2, 64]
    const float* W_cls  = (const float*)d_in[6];   // [192, 40]
    const float* b_cls  = (const float*)d_in[7];   // [40]

    const int N = in_sizes[0] / DH;
    const int E = in_sizes[1] / 2;

    float *hws, *h1, *h2, *ego;
    cudaGetSymbolAddress((void**)&hws, g_hws);
    cudaGetSymbolAddress((void**)&h1,  g_h1);
    cudaGetSymbolAddress((void**)&h2,  g_h2);
    cudaGetSymbolAddress((void**)&ego, g_ego);

    const int T = 256;
    const int NB = (N + T - 1) / T;            // node blocks (<=391)
    const int EB = (E + T - 1) / T;            // edge blocks
    const dim3 gb(16, 16);
    const dim3 cb(10, 16);
    const int tile_blocks = (N + 63) / 64;
    const int agg_blocks = (int)(((long long)N * 32 + T - 1) / T);

    // CSR build + normalization
    k_deg_zero<<<NB, T>>>(ei, N);
    k_count   <<<EB, T>>>(ei, E);
    k_scan1   <<<NB, T>>>(N);
    k_scan2   <<<1, 512>>>(NB);
    k_scan3   <<<NB, T>>>(N);
    k_fill    <<<EB, T>>>(ei, E);

    // hop 1 + ego (fused): hws = dis*(x@Wc0);  ego = relu(x@W_ego + b_ego)
    k_gemm_dual<<<tile_blocks, gb>>>(x, W_conv, W_ego, b_ego, hws, ego, N);
    k_agg      <<<agg_blocks, T>>>(hws, b_conv, h1, N);

    // hop 2
    k_gemm64<<<tile_blocks, gb>>>(h1, W_conv + DH * DH, hws, N);
    k_agg   <<<agg_blocks, T>>>(hws, b_conv + DH, h2, N);

    // classifier
    k_cls<<<tile_blocks, cb>>>(ego, h1, h2, W_cls, b_cls, (float*)d_out, N);
}

// round 6
// speedup vs baseline: 2.4803x; 1.0672x over previous
#include <cuda_runtime.h>
#include <cstdint>

#define MAXN 100000
#define MAXE 1250000
#define DH   64
#define CC   40

// ---------------- device scratch (static; no runtime allocation) -------------
__device__ __align__(16) float g_dis[MAXN];
__device__ int   g_deg[MAXN];
__device__ int   g_rowptr[MAXN + 1];
__device__ int   g_cur[MAXN];
__device__ int   g_csr[MAXE];
__device__ int   g_part[512];
__device__ int   g_is64;
__device__ __align__(16) float g_y [(size_t)MAXN * DH];   // aggregated input
__device__ __align__(16) float g_h1[(size_t)MAXN * DH];   // hop-1 activation

// ---------------- helpers ----------------------------------------------------
__device__ __forceinline__ int edge_at(const void* ei, long long pos) {
    if (g_is64) return (int)((const long long*)ei)[pos];
    return ((const int*)ei)[pos];
}

// deg zero + int64/int32 detection (JAX x64-off silently downcasts) in one pass
__global__ void k_deg_zero(const void* ei, int n) {
    int i = blockIdx.x * blockDim.x + threadIdx.x;
    if (i < n) g_deg[i] = 0;
    if (i == 0) {
        const long long* p = (const long long*)ei;
        int ok = 1;
        #pragma unroll
        for (int k = 0; k < 8; k++) {
            long long v = p[k];
            if (v < 0 || v >= (long long)n) ok = 0;
        }
        g_is64 = ok;
    }
}

__global__ void k_count(const void* ei, int E) {
    int e = blockIdx.x * blockDim.x + threadIdx.x;
    if (e < E) atomicAdd(&g_deg[edge_at(ei, (long long)E + e)], 1);
}

// ---- 3-kernel exclusive scan of g_deg -> g_rowptr / g_cur; also g_dis -------
__global__ void k_scan1(int n) {
    __shared__ int s[256];
    int i = blockIdx.x * 256 + threadIdx.x;
    s[threadIdx.x] = (i < n) ? g_deg[i] : 0;
    __syncthreads();
    #pragma unroll
    for (int off = 128; off > 0; off >>= 1) {
        if (threadIdx.x < off) s[threadIdx.x] += s[threadIdx.x + off];
        __syncthreads();
    }
    if (threadIdx.x == 0) g_part[blockIdx.x] = s[0];
}

__global__ void k_scan2(int nb) {
    __shared__ int s[512];
    int t = threadIdx.x;
    int v = (t < nb) ? g_part[t] : 0;
    s[t] = v;
    __syncthreads();
    #pragma unroll
    for (int off = 1; off < 512; off <<= 1) {
        int add = (t >= off) ? s[t - off] : 0;
        __syncthreads();
        s[t] += add;
        __syncthreads();
    }
    if (t < nb) g_part[t] = s[t] - v;
}

__global__ void k_scan3(int n) {
    __shared__ int s[256];
    int t = threadIdx.x;
    int i = blockIdx.x * 256 + t;
    int v = (i < n) ? g_deg[i] : 0;
    s[t] = v;
    __syncthreads();
    #pragma unroll
    for (int off = 1; off < 256; off <<= 1) {
        int add = (t >= off) ? s[t - off] : 0;
        __syncthreads();
        s[t] += add;
        __syncthreads();
    }
    if (i < n) {
        int base = g_part[blockIdx.x];
        int excl = base + s[t] - v;
        g_rowptr[i] = excl;
        g_cur[i]    = excl;
        g_dis[i]    = rsqrtf((float)(v + 1));     // +1 = self-loop
        if (i == n - 1) g_rowptr[n] = excl + v;
    }
}

__global__ void k_fill(const void* ei, int E) {
    int e = blockIdx.x * blockDim.x + threadIdx.x;
    if (e < E) {
        int r = edge_at(ei, (long long)e);
        int c = edge_at(ei, (long long)E + e);
        int pos = atomicAdd(&g_cur[c], 1);
        g_csr[pos] = r;
    }
}

// -------- gather-first aggregation: y_i = dis_i*src_i + sum_nbr dis_r*src_r ---
// warp per node; each lane owns a float2.
__global__ void k_agg(const float* __restrict__ src, float* __restrict__ y, int n)
{
    int w = (blockIdx.x * blockDim.x + threadIdx.x) >> 5;
    int lane = threadIdx.x & 31;
    if (w >= n) return;

    const float2* H = (const float2*)src;
    float  dw = g_dis[w];
    float2 v0 = H[(size_t)w * 32 + lane];
    float2 acc;
    acc.x = dw * v0.x;
    acc.y = dw * v0.y;

    int p   = g_rowptr[w];
    int end = g_rowptr[w + 1];
    for (; p + 3 < end; p += 4) {
        int s0 = __ldg(&g_csr[p]);
        int s1 = __ldg(&g_csr[p + 1]);
        int s2 = __ldg(&g_csr[p + 2]);
        int s3 = __ldg(&g_csr[p + 3]);
        float d0 = __ldg(&g_dis[s0]);
        float d1 = __ldg(&g_dis[s1]);
        float d2 = __ldg(&g_dis[s2]);
        float d3 = __ldg(&g_dis[s3]);
        float2 a = H[(size_t)s0 * 32 + lane];
        float2 b = H[(size_t)s1 * 32 + lane];
        float2 c = H[(size_t)s2 * 32 + lane];
        float2 d = H[(size_t)s3 * 32 + lane];
        acc.x = fmaf(d0, a.x, fmaf(d1, b.x, fmaf(d2, c.x, fmaf(d3, d.x, acc.x))));
        acc.y = fmaf(d0, a.y, fmaf(d1, b.y, fmaf(d2, c.y, fmaf(d3, d.y, acc.y))));
    }
    for (; p < end; p++) {
        int s0 = __ldg(&g_csr[p]);
        float d0 = __ldg(&g_dis[s0]);
        float2 a = H[(size_t)s0 * 32 + lane];
        acc.x = fmaf(d0, a.x, acc.x);
        acc.y = fmaf(d0, a.y, acc.y);
    }
    ((float2*)y)[(size_t)w * 32 + lane] = acc;
}

// ------------- GEMM+finish: h = relu(dis_i * (y @ W) + b) --------------------
// block (16,16), 64-row tile, k-step-4 float4 inner loop.
__global__ void k_gemm_h(const float* __restrict__ Y, const float* __restrict__ W,
                         const float* __restrict__ bias, float* __restrict__ out, int n)
{
    __shared__ float  Xs[64 * 64];
    __shared__ float4 Ws[64 * 16];

    const int tx = threadIdx.x, ty = threadIdx.y;
    const int tid = ty * 16 + tx;

    const float4* Wv = (const float4*)W;
    #pragma unroll
    for (int i = 0; i < 4; i++) Ws[tid + i * 256] = Wv[tid + i * 256];

    const int r0 = blockIdx.x * 64;
    #pragma unroll
    for (int i = 0; i < 4; i++) {
        int idx = tid + i * 256;
        int rr = idx >> 4, cc = idx & 15;
        int gr = r0 + rr;
        float4 v = make_float4(0.f, 0.f, 0.f, 0.f);
        if (gr < n) v = ((const float4*)(Y + (size_t)gr * DH))[cc];
        *(float4*)&Xs[rr * 64 + cc * 4] = v;
    }
    __syncthreads();

    float4 acc[4];
    #pragma unroll
    for (int i = 0; i < 4; i++) acc[i] = make_float4(0.f, 0.f, 0.f, 0.f);

    #pragma unroll
    for (int k4 = 0; k4 < 16; k4++) {
        float4 xv[4];
        #pragma unroll
        for (int i = 0; i < 4; i++)
            xv[i] = *(const float4*)&Xs[(ty * 4 + i) * 64 + k4 * 4];
        #pragma unroll
        for (int j = 0; j < 4; j++) {
            float4 w = Ws[(k4 * 4 + j) * 16 + tx];
            #pragma unroll
            for (int i = 0; i < 4; i++) {
                float xs = (j == 0) ? xv[i].x : (j == 1) ? xv[i].y : (j == 2) ? xv[i].z : xv[i].w;
                acc[i].x = fmaf(xs, w.x, acc[i].x);
                acc[i].y = fmaf(xs, w.y, acc[i].y);
                acc[i].z = fmaf(xs, w.z, acc[i].z);
                acc[i].w = fmaf(xs, w.w, acc[i].w);
            }
        }
    }

    float4 b = ((const float4*)bias)[tx];
    #pragma unroll
    for (int i = 0; i < 4; i++) {
        int gr = r0 + ty * 4 + i;
        if (gr >= n) continue;
        float s = g_dis[gr];
        float4 a = acc[i];
        a.x = fmaxf(fmaf(s, a.x, b.x), 0.f);
        a.y = fmaxf(fmaf(s, a.y, b.y), 0.f);
        a.z = fmaxf(fmaf(s, a.z, b.z), 0.f);
        a.w = fmaxf(fmaf(s, a.w, b.w), 0.f);
        ((float4*)(out + (size_t)gr * DH))[tx] = a;
    }
}

// ---------------- fused classifier -------------------------------------------
// out = [ego | h1 | h2] @ W_cls + b_cls, where
//   ego = relu(x @ W_ego + b_ego)      (computed in-register from x tile)
//   h2  = relu(dis*(y2 @ Wc1) + b1)    (computed in-register from y2 tile)
// block (16,16), 64-row tile. smem = 17408 + 30720 = 48128 B.
__global__ void k_cls(const float* __restrict__ x, const float* __restrict__ h1,
                      const float* __restrict__ y2,
                      const float* __restrict__ Wego, const float* __restrict__ bego,
                      const float* __restrict__ Wc1,  const float* __restrict__ bc1,
                      const float* __restrict__ Wcls, const float* __restrict__ bcls,
                      float* __restrict__ out, int n)
{
    __shared__ float  Xs[64 * 68];     // 17408 B: current 64x64 source tile
    __shared__ float4 Wcs[192 * 10];   // 30720 B: full classifier weight

    const int tx = threadIdx.x, ty = threadIdx.y;
    const int tid = ty * 16 + tx;
    const int r0 = blockIdx.x * 64;

    const float4* Wclsv = (const float4*)Wcls;
    #pragma unroll
    for (int i = tid; i < 1920; i += 256) Wcs[i] = Wclsv[i];

    float4 acc[4];
    #pragma unroll
    for (int i = 0; i < 4; i++) acc[i] = make_float4(0.f, 0.f, 0.f, 0.f);

    // ---- tile loader (64 rows x 64 cols of S into Xs) ----
    auto load_tile = [&](const float* S) {
        #pragma unroll
        for (int i = 0; i < 4; i++) {
            int idx = tid + i * 256;
            int rr = idx >> 4, cc = idx & 15;
            int gr = r0 + rr;
            float4 v = make_float4(0.f, 0.f, 0.f, 0.f);
            if (gr < n) v = ((const float4*)(S + (size_t)gr * DH))[cc];
            *(float4*)&Xs[rr * 68 + cc * 4] = v;
        }
    };

    // ---- in-place 64x64 transform of Xs: Xs = act(scale*(Xs@W)+b) ----
    auto transform = [&](const float* W, const float* bias, bool use_dis) {
        const float4* Wv = (const float4*)W;
        float4 t[4];
        #pragma unroll
        for (int i = 0; i < 4; i++) t[i] = make_float4(0.f, 0.f, 0.f, 0.f);
        #pragma unroll
        for (int k4 = 0; k4 < 16; k4++) {
            float4 xv[4];
            #pragma unroll
            for (int i = 0; i < 4; i++)
                xv[i] = *(const float4*)&Xs[(ty * 4 + i) * 68 + k4 * 4];
            #pragma unroll
            for (int j = 0; j < 4; j++) {
                float4 w = __ldg(&Wv[(k4 * 4 + j) * 16 + tx]);
                #pragma unroll
                for (int i = 0; i < 4; i++) {
                    float xs = (j == 0) ? xv[i].x : (j == 1) ? xv[i].y : (j == 2) ? xv[i].z : xv[i].w;
                    t[i].x = fmaf(xs, w.x, t[i].x);
                    t[i].y = fmaf(xs, w.y, t[i].y);
                    t[i].z = fmaf(xs, w.z, t[i].z);
                    t[i].w = fmaf(xs, w.w, t[i].w);
                }
            }
        }
        float4 b = __ldg(&((const float4*)bias)[tx]);
        __syncthreads();               // done reading old Xs
        #pragma unroll
        for (int i = 0; i < 4; i++) {
            int gr = r0 + ty * 4 + i;
            float s = 1.0f;
            if (use_dis) s = (gr < n) ? g_dis[gr] : 0.f;
            float4 a = t[i];
            a.x = fmaxf(fmaf(s, a.x, b.x), 0.f);
            a.y = fmaxf(fmaf(s, a.y, b.y), 0.f);
            a.z = fmaxf(fmaf(s, a.z, b.z), 0.f);
            a.w = fmaxf(fmaf(s, a.w, b.w), 0.f);
            *(float4*)&Xs[(ty * 4 + i) * 68 + tx * 4] = a;
        }
    };

    // ---- classifier partial: acc += Xs @ Wcls[c*64 : (c+1)*64, :] ----
    auto cls_accum = [&](int c) {
        if (tx < 10) {
            #pragma unroll
            for (int k4 = 0; k4 < 16; k4++) {
                float4 xv[4];
                #pragma unroll
                for (int i = 0; i < 4; i++)
                    xv[i] = *(const float4*)&Xs[(ty * 4 + i) * 68 + k4 * 4];
                #pragma unroll
                for (int j = 0; j < 4; j++) {
                    float4 w = Wcs[(c * 64 + k4 * 4 + j) * 10 + tx];
                    #pragma unroll
                    for (int i = 0; i < 4; i++) {
                        float xs = (j == 0) ? xv[i].x : (j == 1) ? xv[i].y : (j == 2) ? xv[i].z : xv[i].w;
                        acc[i].x = fmaf(xs, w.x, acc[i].x);
                        acc[i].y = fmaf(xs, w.y, acc[i].y);
                        acc[i].z = fmaf(xs, w.z, acc[i].z);
                        acc[i].w = fmaf(xs, w.w, acc[i].w);
                    }
                }
            }
        }
    };

    // phase 0: ego = relu(x @ Wego + bego)
    load_tile(x);
    __syncthreads();
    transform(Wego, bego, false);
    __syncthreads();
    cls_accum(0);
    __syncthreads();

    // phase 1: h1 (materialized)
    load_tile(h1);
    __syncthreads();
    cls_accum(1);
    __syncthreads();

    // phase 2: h2 = relu(dis*(y2 @ Wc1) + b1)
    load_tile(y2);
    __syncthreads();
    transform(Wc1, bc1, true);
    __syncthreads();
    cls_accum(2);

    if (tx < 10) {
        float4 b = ((const float4*)bcls)[tx];
        #pragma unroll
        for (int i = 0; i < 4; i++) {
            int gr = r0 + ty * 4 + i;
            if (gr >= n) continue;
            float4 a = acc[i];
            a.x += b.x; a.y += b.y; a.z += b.z; a.w += b.w;
            *(float4*)(out + (size_t)gr * CC + tx * 4) = a;
        }
    }
}

// ---------------- launch -----------------------------------------------------
extern "C" void kernel_launch(void* const* d_in, const int* in_sizes, int n_in,
                              void* d_out, int out_size)
{
    const float* x      = (const float*)d_in[0];
    const void*  ei     = d_in[1];
    const float* W_ego  = (const float*)d_in[2];
    const float* b_ego  = (const float*)d_in[3];
    const float* W_conv = (const float*)d_in[4];   // [2, 64, 64]
    const float* b_conv = (const float*)d_in[5];   // [2, 64]
    const float* W_cls  = (const float*)d_in[6];   // [192, 40]
    const float* b_cls  = (const float*)d_in[7];   // [40]

    const int N = in_sizes[0] / DH;
    const int E = in_sizes[1] / 2;

    float *y, *h1;
    cudaGetSymbolAddress((void**)&y,  g_y);
    cudaGetSymbolAddress((void**)&h1, g_h1);

    const int T = 256;
    const int NB = (N + T - 1) / T;
    const int EB = (E + T - 1) / T;
    const dim3 gb(16, 16);
    const int tile_blocks = (N + 63) / 64;
    const int agg_blocks = (int)(((long long)N * 32 + T - 1) / T);

    // CSR build + normalization
    k_deg_zero<<<NB, T>>>(ei, N);
    k_count   <<<EB, T>>>(ei, E);
    k_scan1   <<<NB, T>>>(N);
    k_scan2   <<<1, 512>>>(NB);
    k_scan3   <<<NB, T>>>(N);
    k_fill    <<<EB, T>>>(ei, E);

    // hop 1: y1 = gather(dis*x);  h1 = relu(dis*(y1@Wc0) + b0)
    k_agg   <<<agg_blocks, T>>>(x, y, N);
    k_gemm_h<<<tile_blocks, gb>>>(y, W_conv, b_conv, h1, N);

    // hop 2: y2 = gather(dis*h1)   (h2 virtualized into k_cls)
    k_agg   <<<agg_blocks, T>>>(h1, y, N);

    // fused classifier: ego from x, h1 direct, h2 from y2
    k_cls<<<tile_blocks, gb>>>(x, h1, y,
                               W_ego, b_ego,
                               W_conv + DH * DH, b_conv + DH,
                               W_cls, b_cls, (float*)d_out, N);
}